// round 1
// baseline (speedup 1.0000x reference)
#include <cuda_runtime.h>
#include <math.h>

#define T_STEPS 64
#define BATCH   512
#define NIMG    (T_STEPS*BATCH)   // 32768
#define HID     112
#define G4      448               // 4*HID
#define NB      (BATCH*10)        // 5120 LSTM rows
#define LSTM_BLOCKS 128
#define ROWS_PER_BLK 40           // 128*40 = 5120
#define RPT 10                    // rows per thread (448 threads = 112 j * 4 row-groups)

// ---- scratch (device globals: allocation-free) ----
__device__ float g_feat1[(size_t)NIMG * 10 * 144];   // 188.7 MB
__device__ float g_feat2[(size_t)NIMG * 20 * 36];    // 94.4 MB
__device__ float g_x   [(size_t)NIMG * 360];         // 47.2 MB  == [t][nb][36]
__device__ float g_gx  [(size_t)T_STEPS * NB * G4];  // 587 MB   precomputed x@Wih^T + b_ih + b_hh
__device__ float g_whhT[HID * G4];                   // transposed W_hh: [k][col]

// ---------------------------------------------------------------------------
// W_hh transpose: (448,112) -> (112,448) so LSTM SMEM loads are coalesced
// ---------------------------------------------------------------------------
__global__ void k_transpose(const float* __restrict__ whh) {
    int idx = blockIdx.x * 256 + threadIdx.x;
    if (idx < HID * G4) {
        int k = idx / G4, col = idx % G4;
        g_whhT[idx] = whh[col * HID + k];
    }
}

// ---------------------------------------------------------------------------
// conv1: (N,1,24,24) -> relu -> pool2 -> (N,10,12,12). 2 images / block.
// ---------------------------------------------------------------------------
__global__ void k_conv1(const float* __restrict__ imgs,
                        const float* __restrict__ w1, const float* __restrict__ b1) {
    __shared__ float sin_[2 * 576];
    __shared__ float sw[90];
    __shared__ float sb[10];
    int tid = threadIdx.x;
    size_t img0 = (size_t)blockIdx.x * 2;
    const float* src = imgs + img0 * 576;
    for (int i = tid; i < 1152; i += 256) sin_[i] = src[i];
    if (tid < 90) sw[tid] = w1[tid];
    if (tid < 10) sb[tid] = b1[tid];
    __syncthreads();

    for (int it = tid; it < 288; it += 256) {
        int ii = it / 144, p = it % 144;
        int ph = p / 12, pw = p % 12;
        int y0 = 2 * ph - 1, x0 = 2 * pw - 1;
        float patch[4][4];
        #pragma unroll
        for (int dy = 0; dy < 4; dy++) {
            int y = y0 + dy;
            #pragma unroll
            for (int dx = 0; dx < 4; dx++) {
                int x = x0 + dx;
                patch[dy][dx] = (y >= 0 && y < 24 && x >= 0 && x < 24)
                                ? sin_[ii * 576 + y * 24 + x] : 0.f;
            }
        }
        size_t obase = (img0 + ii) * (10 * 144);
        for (int oc = 0; oc < 10; oc++) {
            float w[9];
            #pragma unroll
            for (int q = 0; q < 9; q++) w[q] = sw[oc * 9 + q];
            float bb = sb[oc];
            float mx = 0.f;  // relu floor; max(relu(v)) == max(0, max v)
            #pragma unroll
            for (int py = 0; py < 2; py++)
                #pragma unroll
                for (int px = 0; px < 2; px++) {
                    float v = bb;
                    #pragma unroll
                    for (int dy = 0; dy < 3; dy++)
                        #pragma unroll
                        for (int dx = 0; dx < 3; dx++)
                            v = fmaf(patch[py + dy][px + dx], w[dy * 3 + dx], v);
                    mx = fmaxf(mx, v);
                }
            g_feat1[obase + oc * 144 + p] = mx;
        }
    }
}

// ---------------------------------------------------------------------------
// conv2: (N,10,12,12) -> relu -> pool2 -> (N,20,6,6). 2 images / block.
// work item = one pooled position x 4 output channels (input-patch reuse)
// ---------------------------------------------------------------------------
__global__ void k_conv2(const float* __restrict__ w2, const float* __restrict__ b2) {
    __shared__ float sin_[2 * 1440];
    __shared__ float sw[1800];
    __shared__ float sb[20];
    int tid = threadIdx.x;
    size_t img0 = (size_t)blockIdx.x * 2;
    const float* src = g_feat1 + img0 * 1440;
    for (int i = tid; i < 2880; i += 256) sin_[i] = src[i];
    for (int i = tid; i < 1800; i += 256) sw[i] = w2[i];
    if (tid < 20) sb[tid] = b2[tid];
    __syncthreads();

    for (int it = tid; it < 360; it += 256) {
        int ii = it / 180, r = it % 180;
        int ocg = r / 36, p = r % 36;
        int ph = p / 6, pw = p % 6;
        int y0 = 2 * ph - 1, x0 = 2 * pw - 1;
        float acc[4][4];
        #pragma unroll
        for (int o = 0; o < 4; o++) {
            float bb = sb[ocg * 4 + o];
            #pragma unroll
            for (int s = 0; s < 4; s++) acc[o][s] = bb;
        }
        for (int ic = 0; ic < 10; ic++) {
            float patch[4][4];
            const float* sp = sin_ + ii * 1440 + ic * 144;
            #pragma unroll
            for (int dy = 0; dy < 4; dy++) {
                int y = y0 + dy;
                #pragma unroll
                for (int dx = 0; dx < 4; dx++) {
                    int x = x0 + dx;
                    patch[dy][dx] = (y >= 0 && y < 12 && x >= 0 && x < 12) ? sp[y * 12 + x] : 0.f;
                }
            }
            #pragma unroll
            for (int o = 0; o < 4; o++) {
                const float* wp = sw + ((ocg * 4 + o) * 10 + ic) * 9;
                float w[9];
                #pragma unroll
                for (int q = 0; q < 9; q++) w[q] = wp[q];
                #pragma unroll
                for (int py = 0; py < 2; py++)
                    #pragma unroll
                    for (int px = 0; px < 2; px++) {
                        float v = acc[o][py * 2 + px];
                        #pragma unroll
                        for (int dy = 0; dy < 3; dy++)
                            #pragma unroll
                            for (int dx = 0; dx < 3; dx++)
                                v = fmaf(patch[py + dy][px + dx], w[dy * 3 + dx], v);
                        acc[o][py * 2 + px] = v;
                    }
            }
        }
        size_t obase = (img0 + ii) * (20 * 36);
        #pragma unroll
        for (int o = 0; o < 4; o++) {
            float mx = fmaxf(fmaxf(acc[o][0], acc[o][1]), fmaxf(acc[o][2], acc[o][3]));
            g_feat2[obase + (ocg * 4 + o) * 36 + p] = fmaxf(mx, 0.f);
        }
    }
}

// ---------------------------------------------------------------------------
// conv3: (N,20,6,6) -> relu -> pool2 -> (N,40,3,3) stored flat into g_x.
// 4 images / block.
// ---------------------------------------------------------------------------
__global__ void k_conv3(const float* __restrict__ w3, const float* __restrict__ b3) {
    __shared__ float sin_[4 * 720];
    __shared__ float sw[7200];
    __shared__ float sb[40];
    int tid = threadIdx.x;
    size_t img0 = (size_t)blockIdx.x * 4;
    const float* src = g_feat2 + img0 * 720;
    for (int i = tid; i < 2880; i += 256) sin_[i] = src[i];
    for (int i = tid; i < 7200; i += 256) sw[i] = w3[i];
    if (tid < 40) sb[tid] = b3[tid];
    __syncthreads();

    for (int it = tid; it < 360; it += 256) {
        int ii = it / 90, r = it % 90;
        int ocg = r / 9, p = r % 9;
        int ph = p / 3, pw = p % 3;
        int y0 = 2 * ph - 1, x0 = 2 * pw - 1;
        float acc[4][4];
        #pragma unroll
        for (int o = 0; o < 4; o++) {
            float bb = sb[ocg * 4 + o];
            #pragma unroll
            for (int s = 0; s < 4; s++) acc[o][s] = bb;
        }
        for (int ic = 0; ic < 20; ic++) {
            float patch[4][4];
            const float* sp = sin_ + ii * 720 + ic * 36;
            #pragma unroll
            for (int dy = 0; dy < 4; dy++) {
                int y = y0 + dy;
                #pragma unroll
                for (int dx = 0; dx < 4; dx++) {
                    int x = x0 + dx;
                    patch[dy][dx] = (y >= 0 && y < 6 && x >= 0 && x < 6) ? sp[y * 6 + x] : 0.f;
                }
            }
            #pragma unroll
            for (int o = 0; o < 4; o++) {
                const float* wp = sw + ((ocg * 4 + o) * 20 + ic) * 9;
                float w[9];
                #pragma unroll
                for (int q = 0; q < 9; q++) w[q] = wp[q];
                #pragma unroll
                for (int py = 0; py < 2; py++)
                    #pragma unroll
                    for (int px = 0; px < 2; px++) {
                        float v = acc[o][py * 2 + px];
                        #pragma unroll
                        for (int dy = 0; dy < 3; dy++)
                            #pragma unroll
                            for (int dx = 0; dx < 3; dx++)
                                v = fmaf(patch[py + dy][px + dx], w[dy * 3 + dx], v);
                        acc[o][py * 2 + px] = v;
                    }
            }
        }
        size_t obase = (img0 + ii) * 360;
        #pragma unroll
        for (int o = 0; o < 4; o++) {
            float mx = fmaxf(fmaxf(acc[o][0], acc[o][1]), fmaxf(acc[o][2], acc[o][3]));
            g_x[obase + (ocg * 4 + o) * 9 + p] = fmaxf(mx, 0.f);
        }
    }
}

// ---------------------------------------------------------------------------
// gates_x precompute for ALL timesteps: (327680,36) @ (36,448) + b_ih + b_hh.
// 448 threads: thread j holds W_ih row j (36 regs); x rows broadcast from SMEM.
// ---------------------------------------------------------------------------
__global__ void k_gatesx(const float* __restrict__ w_ih,
                         const float* __restrict__ b_ih, const float* __restrict__ b_hh) {
    __shared__ float sx[64 * 36];
    int j = threadIdx.x;  // 0..447
    size_t row0 = (size_t)blockIdx.x * 64;
    const float* src = g_x + row0 * 36;
    for (int i = j; i < 2304; i += 448) sx[i] = src[i];
    float w[36];
    const float4* wp = (const float4*)(w_ih + j * 36);
    #pragma unroll
    for (int q = 0; q < 9; q++) {
        float4 v = wp[q];
        w[4 * q] = v.x; w[4 * q + 1] = v.y; w[4 * q + 2] = v.z; w[4 * q + 3] = v.w;
    }
    float bias = b_ih[j] + b_hh[j];
    __syncthreads();
    for (int r = 0; r < 64; r++) {
        const float4* xr = (const float4*)(sx + r * 36);
        float acc = bias;
        #pragma unroll
        for (int q = 0; q < 9; q++) {
            float4 v = xr[q];
            acc = fmaf(v.x, w[4 * q], acc);
            acc = fmaf(v.y, w[4 * q + 1], acc);
            acc = fmaf(v.z, w[4 * q + 2], acc);
            acc = fmaf(v.w, w[4 * q + 3], acc);
        }
        g_gx[(row0 + r) * G4 + j] = acc;
    }
}

// ---------------------------------------------------------------------------
// Whole LSTM recurrence in ONE kernel (rows are independent):
// block = 40 rows, 448 threads (j = tid%112, 4 row-groups of 10 rows).
// W_hh (200.7 KB) + h tile in SMEM; c in registers; 64 steps internal;
// fused final linear + softmax.
// ---------------------------------------------------------------------------
__global__ void __launch_bounds__(448, 1)
k_lstm(const float* __restrict__ h0, const float* __restrict__ c0,
       const float* __restrict__ wf, const float* __restrict__ bf,
       float* __restrict__ out) {
    extern __shared__ float sm[];
    float* ws = sm;                 // [112][448]
    float* hs = sm + HID * G4;      // [40][112]
    int tid = threadIdx.x;
    int j = tid % 112, ry = tid / 112;
    int mb = blockIdx.x * ROWS_PER_BLK;

    // load transposed W_hh into SMEM (coalesced float4)
    {
        const float4* wsrc = (const float4*)g_whhT;
        float4* wdst = (float4*)ws;
        for (int i = tid; i < HID * G4 / 4; i += 448) wdst[i] = wsrc[i];
    }
    // init h, c (broadcast of h0/c0)
    float c[RPT];
    float h0j = h0[j], c0j = c0[j];
    #pragma unroll
    for (int i = 0; i < RPT; i++) {
        hs[(ry * RPT + i) * 112 + j] = h0j;
        c[i] = c0j;
    }
    __syncthreads();

    for (int t = 0; t < T_STEPS; t++) {
        float acc[RPT][4];
        #pragma unroll
        for (int i = 0; i < RPT; i++)
            #pragma unroll
            for (int g = 0; g < 4; g++) acc[i][g] = 0.f;

        const float4* hs4 = (const float4*)hs;
        #pragma unroll 1
        for (int q = 0; q < 28; q++) {
            float4 h4[RPT];
            #pragma unroll
            for (int i = 0; i < RPT; i++) h4[i] = hs4[(ry * RPT + i) * 28 + q];
            const float* wrow = ws + (4 * q) * G4 + j;
            #pragma unroll
            for (int kk = 0; kk < 4; kk++) {
                float w0 = wrow[kk * G4];
                float w1 = wrow[kk * G4 + 112];
                float w2 = wrow[kk * G4 + 224];
                float w3 = wrow[kk * G4 + 336];
                #pragma unroll
                for (int i = 0; i < RPT; i++) {
                    float hv = (kk == 0) ? h4[i].x : (kk == 1) ? h4[i].y
                             : (kk == 2) ? h4[i].z : h4[i].w;
                    acc[i][0] = fmaf(hv, w0, acc[i][0]);
                    acc[i][1] = fmaf(hv, w1, acc[i][1]);
                    acc[i][2] = fmaf(hv, w2, acc[i][2]);
                    acc[i][3] = fmaf(hv, w3, acc[i][3]);
                }
            }
        }
        __syncthreads();  // all reads of hs complete before overwrite

        const float* gxbase = g_gx + ((size_t)t * NB + mb) * G4 + j;
        #pragma unroll
        for (int i = 0; i < RPT; i++) {
            int ml = ry * RPT + i;
            const float* gp = gxbase + (size_t)ml * G4;
            float gi = acc[i][0] + gp[0];
            float gf = acc[i][1] + gp[112];
            float gg = acc[i][2] + gp[224];
            float go = acc[i][3] + gp[336];
            float I = 1.f / (1.f + expf(-gi));
            float F = 1.f / (1.f + expf(-gf));
            float Gv = tanhf(gg);
            float O = 1.f / (1.f + expf(-go));
            c[i] = fmaf(F, c[i], I * Gv);
            hs[ml * 112 + j] = O * tanhf(c[i]);
        }
        __syncthreads();
    }

    // fused final: softmax(h @ wf^T + bf)
    if (tid < ROWS_PER_BLK) {
        const float* hr = hs + tid * 112;
        float l[3];
        #pragma unroll
        for (int o = 0; o < 3; o++) {
            float a = bf[o];
            const float* wo = wf + o * 112;
            #pragma unroll 4
            for (int k = 0; k < 112; k++) a = fmaf(hr[k], wo[k], a);
            l[o] = a;
        }
        float m = fmaxf(l[0], fmaxf(l[1], l[2]));
        float e0 = expf(l[0] - m), e1 = expf(l[1] - m), e2 = expf(l[2] - m);
        float s = 1.f / (e0 + e1 + e2);
        float* op = out + (size_t)(mb + tid) * 3;
        op[0] = e0 * s; op[1] = e1 * s; op[2] = e2 * s;
    }
}

// ---------------------------------------------------------------------------
extern "C" void kernel_launch(void* const* d_in, const int* in_sizes, int n_in,
                              void* d_out, int out_size) {
    const float* imgs = (const float*)d_in[0];
    const float* w1   = (const float*)d_in[1];
    const float* b1   = (const float*)d_in[2];
    const float* w2   = (const float*)d_in[3];
    const float* b2   = (const float*)d_in[4];
    const float* w3   = (const float*)d_in[5];
    const float* b3   = (const float*)d_in[6];
    const float* w_ih = (const float*)d_in[7];
    const float* w_hh = (const float*)d_in[8];
    const float* b_ih = (const float*)d_in[9];
    const float* b_hh = (const float*)d_in[10];
    const float* wf   = (const float*)d_in[11];
    const float* bf   = (const float*)d_in[12];
    const float* h0   = (const float*)d_in[13];
    const float* c0   = (const float*)d_in[14];

    const int lstm_smem = (HID * G4 + ROWS_PER_BLK * HID) * 4;  // 218,624 B
    cudaFuncSetAttribute(k_lstm, cudaFuncAttributeMaxDynamicSharedMemorySize, lstm_smem);

    k_transpose<<<(HID * G4 + 255) / 256, 256>>>(w_hh);
    k_conv1<<<NIMG / 2, 256>>>(imgs, w1, b1);
    k_conv2<<<NIMG / 2, 256>>>(w2, b2);
    k_conv3<<<NIMG / 4, 256>>>(w3, b3);
    k_gatesx<<<(T_STEPS * NB) / 64, 448>>>(w_ih, b_ih, b_hh);
    k_lstm<<<LSTM_BLOCKS, 448, lstm_smem>>>(h0, c0, wf, bf, (float*)d_out);
}

// round 2
// speedup vs baseline: 1.1220x; 1.1220x over previous
#include <cuda_runtime.h>
#include <math.h>

#define T_STEPS 64
#define BATCH   512
#define NIMG    (T_STEPS*BATCH)   // 32768
#define HID     112
#define G4      448               // 4*HID
#define NB      (BATCH*10)        // 5120 LSTM rows
#define LSTM_BLOCKS 128
#define ROWS_PER_BLK 40           // 128*40 = 5120
#define RPT 10                    // rows per thread group

typedef unsigned long long ull;

// ---- f32x2 helpers (Blackwell packed fp32) ----
__device__ __forceinline__ ull pack2(float lo, float hi) {
    ull r;
    asm("mov.b64 %0, {%1, %2};" : "=l"(r) : "r"(__float_as_uint(lo)), "r"(__float_as_uint(hi)));
    return r;
}
__device__ __forceinline__ ull dup2(float v) { return pack2(v, v); }
__device__ __forceinline__ void fma2(ull& d, ull a, ull b) {
    asm("fma.rn.f32x2 %0, %1, %2, %0;" : "+l"(d) : "l"(a), "l"(b));
}
__device__ __forceinline__ void unpack2(ull v, float& lo, float& hi) {
    unsigned ulo, uhi;
    asm("mov.b64 {%0, %1}, %2;" : "=r"(ulo), "=r"(uhi) : "l"(v));
    lo = __uint_as_float(ulo); hi = __uint_as_float(uhi);
}

// fast activations (rel err ~1e-6, well under 1e-3 budget)
__device__ __forceinline__ float fsig(float x) {
    return __fdividef(1.f, 1.f + __expf(-x));
}
__device__ __forceinline__ float ftanh(float x) {
    float e = __expf(2.f * x);
    return 1.f - __fdividef(2.f, e + 1.f);
}

// ---- scratch (device globals: allocation-free) ----
__device__ float g_feat1[(size_t)NIMG * 10 * 144];   // 188.7 MB
__device__ float g_feat2[(size_t)NIMG * 20 * 36];    // 94.4 MB
__device__ float g_x   [(size_t)NIMG * 360];         // 47.2 MB
__device__ float g_gx  [(size_t)T_STEPS * NB * G4];  // 587 MB
__device__ float g_whhT[HID * G4];                   // transposed W_hh: [k][col]

// ---------------------------------------------------------------------------
__global__ void k_transpose(const float* __restrict__ whh) {
    int idx = blockIdx.x * 256 + threadIdx.x;
    if (idx < HID * G4) {
        int k = idx / G4, col = idx % G4;
        g_whhT[idx] = whh[col * HID + k];
    }
}

// ---------------------------------------------------------------------------
// conv1: (N,1,24,24) -> relu -> pool2 -> (N,10,12,12). 2 images / block.
// f32x2: pack the 2 pooling columns.
// ---------------------------------------------------------------------------
__global__ void k_conv1(const float* __restrict__ imgs,
                        const float* __restrict__ w1, const float* __restrict__ b1) {
    __shared__ float sin_[2 * 576];
    __shared__ float sw[90];
    __shared__ float sb[10];
    int tid = threadIdx.x;
    size_t img0 = (size_t)blockIdx.x * 2;
    const float* src = imgs + img0 * 576;
    for (int i = tid; i < 1152; i += 256) sin_[i] = src[i];
    if (tid < 90) sw[tid] = w1[tid];
    if (tid < 10) sb[tid] = b1[tid];
    __syncthreads();

    for (int it = tid; it < 288; it += 256) {
        int ii = it / 144, p = it % 144;
        int ph = p / 12, pw = p % 12;
        int y0 = 2 * ph - 1, x0 = 2 * pw - 1;
        float patch[4][4];
        #pragma unroll
        for (int dy = 0; dy < 4; dy++) {
            int y = y0 + dy;
            #pragma unroll
            for (int dx = 0; dx < 4; dx++) {
                int x = x0 + dx;
                patch[dy][dx] = (y >= 0 && y < 24 && x >= 0 && x < 24)
                                ? sin_[ii * 576 + y * 24 + x] : 0.f;
            }
        }
        ull pp[4][3];
        #pragma unroll
        for (int r = 0; r < 4; r++)
            #pragma unroll
            for (int dx = 0; dx < 3; dx++)
                pp[r][dx] = pack2(patch[r][dx], patch[r][dx + 1]);

        size_t obase = (img0 + ii) * (10 * 144);
        for (int oc = 0; oc < 10; oc++) {
            float w[9];
            #pragma unroll
            for (int q = 0; q < 9; q++) w[q] = sw[oc * 9 + q];
            float bb = sb[oc];
            ull acc0 = dup2(bb), acc1 = dup2(bb);
            #pragma unroll
            for (int dy = 0; dy < 3; dy++)
                #pragma unroll
                for (int dx = 0; dx < 3; dx++) {
                    ull wd = dup2(w[dy * 3 + dx]);
                    fma2(acc0, pp[dy][dx], wd);
                    fma2(acc1, pp[dy + 1][dx], wd);
                }
            float v00, v01, v10, v11;
            unpack2(acc0, v00, v01); unpack2(acc1, v10, v11);
            float mx = fmaxf(fmaxf(v00, v01), fmaxf(v10, v11));
            g_feat1[obase + oc * 144 + p] = fmaxf(mx, 0.f);
        }
    }
}

// ---------------------------------------------------------------------------
// conv2: (N,10,12,12) -> relu -> pool2 -> (N,20,6,6). 2 images / block.
// ---------------------------------------------------------------------------
__global__ void k_conv2(const float* __restrict__ w2, const float* __restrict__ b2) {
    __shared__ float sin_[2 * 1440];
    __shared__ float sw[1800];
    __shared__ float sb[20];
    int tid = threadIdx.x;
    size_t img0 = (size_t)blockIdx.x * 2;
    const float* src = g_feat1 + img0 * 1440;
    for (int i = tid; i < 2880; i += 256) sin_[i] = src[i];
    for (int i = tid; i < 1800; i += 256) sw[i] = w2[i];
    if (tid < 20) sb[tid] = b2[tid];
    __syncthreads();

    for (int it = tid; it < 360; it += 256) {
        int ii = it / 180, r = it % 180;
        int ocg = r / 36, p = r % 36;
        int ph = p / 6, pw = p % 6;
        int y0 = 2 * ph - 1, x0 = 2 * pw - 1;
        ull accp[4][2];
        #pragma unroll
        for (int o = 0; o < 4; o++) {
            ull bb = dup2(sb[ocg * 4 + o]);
            accp[o][0] = bb; accp[o][1] = bb;
        }
        for (int ic = 0; ic < 10; ic++) {
            float patch[4][4];
            const float* sp = sin_ + ii * 1440 + ic * 144;
            #pragma unroll
            for (int dy = 0; dy < 4; dy++) {
                int y = y0 + dy;
                #pragma unroll
                for (int dx = 0; dx < 4; dx++) {
                    int x = x0 + dx;
                    patch[dy][dx] = (y >= 0 && y < 12 && x >= 0 && x < 12) ? sp[y * 12 + x] : 0.f;
                }
            }
            ull pp[4][3];
            #pragma unroll
            for (int rr = 0; rr < 4; rr++)
                #pragma unroll
                for (int dx = 0; dx < 3; dx++)
                    pp[rr][dx] = pack2(patch[rr][dx], patch[rr][dx + 1]);
            #pragma unroll
            for (int o = 0; o < 4; o++) {
                const float* wp = sw + ((ocg * 4 + o) * 10 + ic) * 9;
                #pragma unroll
                for (int dy = 0; dy < 3; dy++)
                    #pragma unroll
                    for (int dx = 0; dx < 3; dx++) {
                        ull wd = dup2(wp[dy * 3 + dx]);
                        fma2(accp[o][0], pp[dy][dx], wd);
                        fma2(accp[o][1], pp[dy + 1][dx], wd);
                    }
            }
        }
        size_t obase = (img0 + ii) * (20 * 36);
        #pragma unroll
        for (int o = 0; o < 4; o++) {
            float v00, v01, v10, v11;
            unpack2(accp[o][0], v00, v01); unpack2(accp[o][1], v10, v11);
            float mx = fmaxf(fmaxf(v00, v01), fmaxf(v10, v11));
            g_feat2[obase + (ocg * 4 + o) * 36 + p] = fmaxf(mx, 0.f);
        }
    }
}

// ---------------------------------------------------------------------------
// conv3: (N,20,6,6) -> relu -> pool2 -> (N,40,3,3) -> g_x. 4 images / block.
// ---------------------------------------------------------------------------
__global__ void k_conv3(const float* __restrict__ w3, const float* __restrict__ b3) {
    __shared__ float sin_[4 * 720];
    __shared__ float sw[7200];
    __shared__ float sb[40];
    int tid = threadIdx.x;
    size_t img0 = (size_t)blockIdx.x * 4;
    const float* src = g_feat2 + img0 * 720;
    for (int i = tid; i < 2880; i += 256) sin_[i] = src[i];
    for (int i = tid; i < 7200; i += 256) sw[i] = w3[i];
    if (tid < 40) sb[tid] = b3[tid];
    __syncthreads();

    for (int it = tid; it < 360; it += 256) {
        int ii = it / 90, r = it % 90;
        int ocg = r / 9, p = r % 9;
        int ph = p / 3, pw = p % 3;
        int y0 = 2 * ph - 1, x0 = 2 * pw - 1;
        ull accp[4][2];
        #pragma unroll
        for (int o = 0; o < 4; o++) {
            ull bb = dup2(sb[ocg * 4 + o]);
            accp[o][0] = bb; accp[o][1] = bb;
        }
        for (int ic = 0; ic < 20; ic++) {
            float patch[4][4];
            const float* sp = sin_ + ii * 720 + ic * 36;
            #pragma unroll
            for (int dy = 0; dy < 4; dy++) {
                int y = y0 + dy;
                #pragma unroll
                for (int dx = 0; dx < 4; dx++) {
                    int x = x0 + dx;
                    patch[dy][dx] = (y >= 0 && y < 6 && x >= 0 && x < 6) ? sp[y * 6 + x] : 0.f;
                }
            }
            ull pp[4][3];
            #pragma unroll
            for (int rr = 0; rr < 4; rr++)
                #pragma unroll
                for (int dx = 0; dx < 3; dx++)
                    pp[rr][dx] = pack2(patch[rr][dx], patch[rr][dx + 1]);
            #pragma unroll
            for (int o = 0; o < 4; o++) {
                const float* wp = sw + ((ocg * 4 + o) * 20 + ic) * 9;
                #pragma unroll
                for (int dy = 0; dy < 3; dy++)
                    #pragma unroll
                    for (int dx = 0; dx < 3; dx++) {
                        ull wd = dup2(wp[dy * 3 + dx]);
                        fma2(accp[o][0], pp[dy][dx], wd);
                        fma2(accp[o][1], pp[dy + 1][dx], wd);
                    }
            }
        }
        size_t obase = (img0 + ii) * 360;
        #pragma unroll
        for (int o = 0; o < 4; o++) {
            float v00, v01, v10, v11;
            unpack2(accp[o][0], v00, v01); unpack2(accp[o][1], v10, v11);
            float mx = fmaxf(fmaxf(v00, v01), fmaxf(v10, v11));
            g_x[obase + (ocg * 4 + o) * 9 + p] = fmaxf(mx, 0.f);
        }
    }
}

// ---------------------------------------------------------------------------
// gates_x: (327680,36) @ (36,448) + biases. f32x2 over row pairs.
// SMEM x stored transposed-paired: sxp[k][rp] = (x[2rp][k], x[2rp+1][k]).
// ---------------------------------------------------------------------------
__global__ void __launch_bounds__(448, 1)
k_gatesx(const float* __restrict__ w_ih,
         const float* __restrict__ b_ih, const float* __restrict__ b_hh) {
    __shared__ float sxp[36 * 32 * 2];  // [k][rp] float2 components
    int j = threadIdx.x;  // 0..447
    size_t row0 = (size_t)blockIdx.x * 64;
    const float* src = g_x + row0 * 36;
    for (int i = j; i < 2304; i += 448) {
        int row = i / 36, k = i % 36;
        sxp[(k * 32 + (row >> 1)) * 2 + (row & 1)] = src[i];
    }
    ull wd[36];
    {
        const float4* wp = (const float4*)(w_ih + j * 36);
        #pragma unroll
        for (int q = 0; q < 9; q++) {
            float4 v = wp[q];
            wd[4 * q] = dup2(v.x); wd[4 * q + 1] = dup2(v.y);
            wd[4 * q + 2] = dup2(v.z); wd[4 * q + 3] = dup2(v.w);
        }
    }
    float bias = b_ih[j] + b_hh[j];
    ull bias2 = dup2(bias);
    __syncthreads();

    const ull* sx2 = (const ull*)sxp;
    for (int rp = 0; rp < 32; rp++) {
        ull acc = bias2;
        #pragma unroll
        for (int k = 0; k < 36; k++)
            fma2(acc, sx2[k * 32 + rp], wd[k]);
        float lo, hi; unpack2(acc, lo, hi);
        g_gx[(row0 + 2 * rp) * G4 + j] = lo;
        g_gx[(row0 + 2 * rp + 1) * G4 + j] = hi;
    }
}

// ---------------------------------------------------------------------------
// Full LSTM recurrence in ONE kernel. h stored as row-pairs (float2) so one
// LDS.128 yields packed f32x2 operands for two rows x two k's.
// ---------------------------------------------------------------------------
__global__ void __launch_bounds__(448, 1)
k_lstm(const float* __restrict__ h0, const float* __restrict__ c0,
       const float* __restrict__ wf, const float* __restrict__ bf,
       float* __restrict__ out) {
    extern __shared__ float sm[];
    float* ws = sm;                               // [112][448]
    float2* hs2 = (float2*)(sm + HID * G4);       // [20 pairs][112] float2
    int tid = threadIdx.x;
    int j = tid % 112, ry = tid / 112;
    int mb = blockIdx.x * ROWS_PER_BLK;

    {
        const float4* wsrc = (const float4*)g_whhT;
        float4* wdst = (float4*)ws;
        for (int i = tid; i < HID * G4 / 4; i += 448) wdst[i] = wsrc[i];
    }
    float c[RPT];
    float h0j = h0[j], c0j = c0[j];
    #pragma unroll
    for (int p = 0; p < 5; p++) hs2[(ry * 5 + p) * 112 + j] = make_float2(h0j, h0j);
    #pragma unroll
    for (int i = 0; i < RPT; i++) c[i] = c0j;
    __syncthreads();

    for (int t = 0; t < T_STEPS; t++) {
        ull accp[5][4];
        #pragma unroll
        for (int p = 0; p < 5; p++)
            #pragma unroll
            for (int g = 0; g < 4; g++) accp[p][g] = 0ull;

        const ulonglong2* hv2 = (const ulonglong2*)hs2;
        #pragma unroll 2
        for (int kq = 0; kq < 56; kq++) {
            int k = kq * 2;
            ulonglong2 hv[5];
            #pragma unroll
            for (int p = 0; p < 5; p++)
                hv[p] = hv2[((ry * 5 + p) * 112 + k) >> 1];
            const float* wk = ws + k * G4 + j;
            ull wd0[4], wd1[4];
            #pragma unroll
            for (int g = 0; g < 4; g++) {
                wd0[g] = dup2(wk[g * 112]);
                wd1[g] = dup2(wk[G4 + g * 112]);
            }
            #pragma unroll
            for (int p = 0; p < 5; p++)
                #pragma unroll
                for (int g = 0; g < 4; g++) {
                    fma2(accp[p][g], hv[p].x, wd0[g]);
                    fma2(accp[p][g], hv[p].y, wd1[g]);
                }
        }
        __syncthreads();  // all reads of hs2 done before overwrite

        const float* gxb = g_gx + ((size_t)t * NB + mb + ry * RPT) * G4 + j;
        #pragma unroll
        for (int p = 0; p < 5; p++) {
            float a0[4], a1[4];
            #pragma unroll
            for (int g = 0; g < 4; g++) unpack2(accp[p][g], a0[g], a1[g]);
            const float* gp0 = gxb + (size_t)(2 * p) * G4;
            const float* gp1 = gp0 + G4;

            float I0 = fsig(a0[0] + gp0[0]);
            float F0 = fsig(a0[1] + gp0[112]);
            float G0 = ftanh(a0[2] + gp0[224]);
            float O0 = fsig(a0[3] + gp0[336]);
            c[2 * p] = fmaf(F0, c[2 * p], I0 * G0);
            float hA = O0 * ftanh(c[2 * p]);

            float I1 = fsig(a1[0] + gp1[0]);
            float F1 = fsig(a1[1] + gp1[112]);
            float G1 = ftanh(a1[2] + gp1[224]);
            float O1 = fsig(a1[3] + gp1[336]);
            c[2 * p + 1] = fmaf(F1, c[2 * p + 1], I1 * G1);
            float hB = O1 * ftanh(c[2 * p + 1]);

            hs2[(ry * 5 + p) * 112 + j] = make_float2(hA, hB);
        }
        __syncthreads();
    }

    // fused final: softmax(h @ wf^T + bf)
    if (tid < ROWS_PER_BLK) {
        int pair = tid >> 1, comp = tid & 1;
        float l[3];
        #pragma unroll
        for (int o = 0; o < 3; o++) {
            float a = bf[o];
            const float* wo = wf + o * 112;
            #pragma unroll 4
            for (int k = 0; k < 112; k++) {
                float2 v = hs2[pair * 112 + k];
                a = fmaf(comp ? v.y : v.x, wo[k], a);
            }
            l[o] = a;
        }
        float m = fmaxf(l[0], fmaxf(l[1], l[2]));
        float e0 = expf(l[0] - m), e1 = expf(l[1] - m), e2 = expf(l[2] - m);
        float s = 1.f / (e0 + e1 + e2);
        float* op = out + (size_t)(mb + tid) * 3;
        op[0] = e0 * s; op[1] = e1 * s; op[2] = e2 * s;
    }
}

// ---------------------------------------------------------------------------
extern "C" void kernel_launch(void* const* d_in, const int* in_sizes, int n_in,
                              void* d_out, int out_size) {
    const float* imgs = (const float*)d_in[0];
    const float* w1   = (const float*)d_in[1];
    const float* b1   = (const float*)d_in[2];
    const float* w2   = (const float*)d_in[3];
    const float* b2   = (const float*)d_in[4];
    const float* w3   = (const float*)d_in[5];
    const float* b3   = (const float*)d_in[6];
    const float* w_ih = (const float*)d_in[7];
    const float* w_hh = (const float*)d_in[8];
    const float* b_ih = (const float*)d_in[9];
    const float* b_hh = (const float*)d_in[10];
    const float* wf   = (const float*)d_in[11];
    const float* bf   = (const float*)d_in[12];
    const float* h0   = (const float*)d_in[13];
    const float* c0   = (const float*)d_in[14];

    const int lstm_smem = HID * G4 * 4 + 20 * 112 * 8;  // 218,624 B
    cudaFuncSetAttribute(k_lstm, cudaFuncAttributeMaxDynamicSharedMemorySize, lstm_smem);

    k_transpose<<<(HID * G4 + 255) / 256, 256>>>(w_hh);
    k_conv1<<<NIMG / 2, 256>>>(imgs, w1, b1);
    k_conv2<<<NIMG / 2, 256>>>(w2, b2);
    k_conv3<<<NIMG / 4, 256>>>(w3, b3);
    k_gatesx<<<(T_STEPS * NB) / 64, 448>>>(w_ih, b_ih, b_hh);
    k_lstm<<<LSTM_BLOCKS, 448, lstm_smem>>>(h0, c0, wf, bf, (float*)d_out);
}

// round 5
// speedup vs baseline: 1.1742x; 1.0465x over previous
#include <cuda_runtime.h>
#include <math.h>

#define T_STEPS 64
#define BATCH   512
#define NIMG    (T_STEPS*BATCH)   // 32768
#define HID     112
#define G4      448               // 4*HID
#define NB      (BATCH*10)        // 5120 LSTM rows
#define LSTM_BLOCKS 128
#define ROWS_PER_BLK 40           // 128*40 = 5120
#define RPT 10

typedef unsigned long long ull;

// ---- f32x2 helpers (Blackwell packed fp32) ----
__device__ __forceinline__ ull pack2(float lo, float hi) {
    ull r;
    asm("mov.b64 %0, {%1, %2};" : "=l"(r) : "r"(__float_as_uint(lo)), "r"(__float_as_uint(hi)));
    return r;
}
__device__ __forceinline__ ull dup2(float v) { return pack2(v, v); }
__device__ __forceinline__ void fma2(ull& d, ull a, ull b) {
    asm("fma.rn.f32x2 %0, %1, %2, %0;" : "+l"(d) : "l"(a), "l"(b));
}
__device__ __forceinline__ void unpack2(ull v, float& lo, float& hi) {
    unsigned ulo, uhi;
    asm("mov.b64 {%0, %1}, %2;" : "=r"(ulo), "=r"(uhi) : "l"(v));
    lo = __uint_as_float(ulo); hi = __uint_as_float(uhi);
}

__device__ __forceinline__ float fsig(float x) {
    return __fdividef(1.f, 1.f + __expf(-x));
}
__device__ __forceinline__ float ftanh(float x) {
    float e = __expf(2.f * x);
    return 1.f - __fdividef(2.f, e + 1.f);
}

// ---- scratch ----
__device__ float g_feat1[(size_t)NIMG * 10 * 144];
__device__ float g_feat2[(size_t)NIMG * 20 * 36];
__device__ float g_x   [(size_t)NIMG * 360];
__device__ float g_gx  [(size_t)T_STEPS * NB * G4];
__device__ float g_whhT[HID * G4];

// ---------------------------------------------------------------------------
__global__ void k_transpose(const float* __restrict__ whh) {
    int idx = blockIdx.x * 256 + threadIdx.x;
    if (idx < HID * G4) {
        int k = idx / G4, col = idx % G4;
        g_whhT[idx] = whh[col * HID + k];
    }
}

// ---------------------------------------------------------------------------
// conv1: (N,1,24,24) -> relu -> pool2 -> (N,10,12,12). 2 images / block.
// ---------------------------------------------------------------------------
__global__ void k_conv1(const float* __restrict__ imgs,
                        const float* __restrict__ w1, const float* __restrict__ b1) {
    __shared__ float sin_[2 * 576];
    __shared__ float sw[90];
    __shared__ float sb[10];
    int tid = threadIdx.x;
    size_t img0 = (size_t)blockIdx.x * 2;
    const float* src = imgs + img0 * 576;
    for (int i = tid; i < 1152; i += 256) sin_[i] = src[i];
    if (tid < 90) sw[tid] = w1[tid];
    if (tid < 10) sb[tid] = b1[tid];
    __syncthreads();

    for (int it = tid; it < 288; it += 256) {
        int ii = it / 144, p = it % 144;
        int ph = p / 12, pw = p % 12;
        int y0 = 2 * ph - 1, x0 = 2 * pw - 1;
        float patch[4][4];
        #pragma unroll
        for (int dy = 0; dy < 4; dy++) {
            int y = y0 + dy;
            #pragma unroll
            for (int dx = 0; dx < 4; dx++) {
                int x = x0 + dx;
                patch[dy][dx] = (y >= 0 && y < 24 && x >= 0 && x < 24)
                                ? sin_[ii * 576 + y * 24 + x] : 0.f;
            }
        }
        ull pp[4][3];
        #pragma unroll
        for (int r = 0; r < 4; r++)
            #pragma unroll
            for (int dx = 0; dx < 3; dx++)
                pp[r][dx] = pack2(patch[r][dx], patch[r][dx + 1]);

        size_t obase = (img0 + ii) * (10 * 144);
        for (int oc = 0; oc < 10; oc++) {
            float w[9];
            #pragma unroll
            for (int q = 0; q < 9; q++) w[q] = sw[oc * 9 + q];
            float bb = sb[oc];
            ull acc0 = dup2(bb), acc1 = dup2(bb);
            #pragma unroll
            for (int dy = 0; dy < 3; dy++)
                #pragma unroll
                for (int dx = 0; dx < 3; dx++) {
                    ull wd = dup2(w[dy * 3 + dx]);
                    fma2(acc0, pp[dy][dx], wd);
                    fma2(acc1, pp[dy + 1][dx], wd);
                }
            float v00, v01, v10, v11;
            unpack2(acc0, v00, v01); unpack2(acc1, v10, v11);
            float mx = fmaxf(fmaxf(v00, v01), fmaxf(v10, v11));
            g_feat1[obase + oc * 144 + p] = fmaxf(mx, 0.f);
        }
    }
}

// ---------------------------------------------------------------------------
// conv2: (N,10,12,12) -> relu -> pool2 -> (N,20,6,6). 2 images / block.
// Thread strip = (img, oc-pair, pooled-row, half): 3 pooled cols, 2 oc.
// ---------------------------------------------------------------------------
__global__ void __launch_bounds__(256, 1)
k_conv2(const float* __restrict__ w2, const float* __restrict__ b2) {
    __shared__ __align__(16) float sin_[2 * 1440];
    __shared__ float sw[1800];
    __shared__ float sb[20];
    int tid = threadIdx.x;
    size_t img0 = (size_t)blockIdx.x * 2;
    const float* src = g_feat1 + img0 * 1440;
    for (int i = tid; i < 2880; i += 256) sin_[i] = src[i];
    for (int i = tid; i < 1800; i += 256) sw[i] = w2[i];
    if (tid < 20) sb[tid] = b2[tid];
    __syncthreads();

    if (tid >= 240) return;
    int ii   = tid / 120;
    int rem  = tid % 120;
    int og   = rem / 12;        // 0..9  -> oc pair (2og, 2og+1)
    int rr   = rem % 12;
    int ph   = rr / 2;          // 0..5
    int half = rr % 2;          // pw0 = 3*half

    ull acc[2][3][2];
    #pragma unroll
    for (int o = 0; o < 2; o++) {
        ull bb = dup2(sb[2 * og + o]);
        #pragma unroll
        for (int pw = 0; pw < 3; pw++) { acc[o][pw][0] = bb; acc[o][pw][1] = bb; }
    }

    const float* base = sin_ + ii * 1440;
    #pragma unroll 1
    for (int ic = 0; ic < 10; ic++) {
        const float* sp = base + ic * 144;
        float v[4][8];
        #pragma unroll
        for (int dy = 0; dy < 4; dy++) {
            int y = 2 * ph - 1 + dy;
            if (y >= 0 && y < 12) {
                const float4* rp = (const float4*)(sp + y * 12);
                float4 a = rp[half];
                float4 b = rp[half + 1];
                if (!half) {
                    v[dy][0] = 0.f;  v[dy][1] = a.x; v[dy][2] = a.y; v[dy][3] = a.z;
                    v[dy][4] = a.w;  v[dy][5] = b.x; v[dy][6] = b.y; v[dy][7] = b.z;
                } else {
                    v[dy][0] = a.y;  v[dy][1] = a.z; v[dy][2] = a.w; v[dy][3] = b.x;
                    v[dy][4] = b.y;  v[dy][5] = b.z; v[dy][6] = b.w; v[dy][7] = 0.f;
                }
            } else {
                #pragma unroll
                for (int k = 0; k < 8; k++) v[dy][k] = 0.f;
            }
        }
        ull pk[4][7];
        #pragma unroll
        for (int dy = 0; dy < 4; dy++)
            #pragma unroll
            for (int cc = 0; cc < 7; cc++)
                pk[dy][cc] = pack2(v[dy][cc], v[dy][cc + 1]);

        #pragma unroll
        for (int o = 0; o < 2; o++) {
            const float* wp = sw + ((2 * og + o) * 10 + ic) * 9;
            ull wd[9];
            #pragma unroll
            for (int q = 0; q < 9; q++) wd[q] = dup2(wp[q]);
            #pragma unroll
            for (int pw = 0; pw < 3; pw++)
                #pragma unroll
                for (int r = 0; r < 2; r++)
                    #pragma unroll
                    for (int dy = 0; dy < 3; dy++)
                        #pragma unroll
                        for (int dx = 0; dx < 3; dx++)
                            fma2(acc[o][pw][r], pk[r + dy][2 * pw + dx], wd[dy * 3 + dx]);
        }
    }

    size_t obase = (img0 + ii) * 720;
    #pragma unroll
    for (int o = 0; o < 2; o++)
        #pragma unroll
        for (int pw = 0; pw < 3; pw++) {
            float v00, v01, v10, v11;
            unpack2(acc[o][pw][0], v00, v01);
            unpack2(acc[o][pw][1], v10, v11);
            float mx = fmaxf(fmaxf(v00, v01), fmaxf(v10, v11));
            g_feat2[obase + (2 * og + o) * 36 + ph * 6 + 3 * half + pw] = fmaxf(mx, 0.f);
        }
}

// ---------------------------------------------------------------------------
// conv3: (N,20,6,6) -> relu -> pool2 -> (N,40,3,3) -> g_x. 4 images / block.
// Thread strip = (img, oc-pair, pooled-row): all 3 pooled cols.
// ---------------------------------------------------------------------------
__global__ void __launch_bounds__(256, 1)
k_conv3(const float* __restrict__ w3, const float* __restrict__ b3) {
    __shared__ __align__(16) float sin_[4 * 720];
    __shared__ float sw[7200];
    __shared__ float sb[40];
    int tid = threadIdx.x;
    size_t img0 = (size_t)blockIdx.x * 4;
    const float* src = g_feat2 + img0 * 720;
    for (int i = tid; i < 2880; i += 256) sin_[i] = src[i];
    for (int i = tid; i < 7200; i += 256) sw[i] = w3[i];
    if (tid < 40) sb[tid] = b3[tid];
    __syncthreads();

    if (tid >= 240) return;
    int ii  = tid / 60;
    int rem = tid % 60;
    int og  = rem / 3;   // 0..19 -> oc pair (2og, 2og+1)
    int ph  = rem % 3;

    ull acc[2][3][2];
    #pragma unroll
    for (int o = 0; o < 2; o++) {
        ull bb = dup2(sb[2 * og + o]);
        #pragma unroll
        for (int pw = 0; pw < 3; pw++) { acc[o][pw][0] = bb; acc[o][pw][1] = bb; }
    }

    const float* base = sin_ + ii * 720;
    #pragma unroll 1
    for (int ic = 0; ic < 20; ic++) {
        const float* sp = base + ic * 36;
        float v[4][8];
        #pragma unroll
        for (int dy = 0; dy < 4; dy++) {
            int y = 2 * ph - 1 + dy;
            if (y >= 0 && y < 6) {
                const float2* rp = (const float2*)(sp + y * 6);
                float2 r0 = rp[0], r1 = rp[1], r2 = rp[2];
                v[dy][0] = 0.f;  v[dy][1] = r0.x; v[dy][2] = r0.y; v[dy][3] = r1.x;
                v[dy][4] = r1.y; v[dy][5] = r2.x; v[dy][6] = r2.y; v[dy][7] = 0.f;
            } else {
                #pragma unroll
                for (int k = 0; k < 8; k++) v[dy][k] = 0.f;
            }
        }
        ull pk[4][7];
        #pragma unroll
        for (int dy = 0; dy < 4; dy++)
            #pragma unroll
            for (int cc = 0; cc < 7; cc++)
                pk[dy][cc] = pack2(v[dy][cc], v[dy][cc + 1]);

        #pragma unroll
        for (int o = 0; o < 2; o++) {
            const float* wp = sw + ((2 * og + o) * 20 + ic) * 9;
            ull wd[9];
            #pragma unroll
            for (int q = 0; q < 9; q++) wd[q] = dup2(wp[q]);
            #pragma unroll
            for (int pw = 0; pw < 3; pw++)
                #pragma unroll
                for (int r = 0; r < 2; r++)
                    #pragma unroll
                    for (int dy = 0; dy < 3; dy++)
                        #pragma unroll
                        for (int dx = 0; dx < 3; dx++)
                            fma2(acc[o][pw][r], pk[r + dy][2 * pw + dx], wd[dy * 3 + dx]);
        }
    }

    size_t obase = (img0 + ii) * 360;
    #pragma unroll
    for (int o = 0; o < 2; o++)
        #pragma unroll
        for (int pw = 0; pw < 3; pw++) {
            float v00, v01, v10, v11;
            unpack2(acc[o][pw][0], v00, v01);
            unpack2(acc[o][pw][1], v10, v11);
            float mx = fmaxf(fmaxf(v00, v01), fmaxf(v10, v11));
            g_x[obase + (2 * og + o) * 9 + ph * 3 + pw] = fmaxf(mx, 0.f);
        }
}

// ---------------------------------------------------------------------------
// gates_x: (327680,36) @ (36,448) + biases. f32x2 over row pairs.
// ---------------------------------------------------------------------------
__global__ void __launch_bounds__(448, 1)
k_gatesx(const float* __restrict__ w_ih,
         const float* __restrict__ b_ih, const float* __restrict__ b_hh) {
    __shared__ __align__(16) float sxp[36 * 32 * 2];
    int j = threadIdx.x;
    size_t row0 = (size_t)blockIdx.x * 64;
    const float* src = g_x + row0 * 36;
    for (int i = j; i < 2304; i += 448) {
        int row = i / 36, k = i % 36;
        sxp[(k * 32 + (row >> 1)) * 2 + (row & 1)] = src[i];
    }
    ull wd[36];
    {
        const float4* wp = (const float4*)(w_ih + j * 36);
        #pragma unroll
        for (int q = 0; q < 9; q++) {
            float4 v = wp[q];
            wd[4 * q] = dup2(v.x); wd[4 * q + 1] = dup2(v.y);
            wd[4 * q + 2] = dup2(v.z); wd[4 * q + 3] = dup2(v.w);
        }
    }
    float bias = b_ih[j] + b_hh[j];
    ull bias2 = dup2(bias);
    __syncthreads();

    const ull* sx2 = (const ull*)sxp;
    for (int rp = 0; rp < 32; rp++) {
        ull acc = bias2;
        #pragma unroll
        for (int k = 0; k < 36; k++)
            fma2(acc, sx2[k * 32 + rp], wd[k]);
        float lo, hi; unpack2(acc, lo, hi);
        g_gx[(row0 + 2 * rp) * G4 + j] = lo;
        g_gx[(row0 + 2 * rp + 1) * G4 + j] = hi;
    }
}

// ---------------------------------------------------------------------------
// Full LSTM recurrence in ONE kernel.
// ---------------------------------------------------------------------------
__global__ void __launch_bounds__(448, 1)
k_lstm(const float* __restrict__ h0, const float* __restrict__ c0,
       const float* __restrict__ wf, const float* __restrict__ bf,
       float* __restrict__ out) {
    extern __shared__ float sm[];
    float* ws = sm;                               // [112][448]
    float2* hs2 = (float2*)(sm + HID * G4);       // [20 pairs][112]
    int tid = threadIdx.x;
    int j = tid % 112, ry = tid / 112;
    int mb = blockIdx.x * ROWS_PER_BLK;

    {
        const float4* wsrc = (const float4*)g_whhT;
        float4* wdst = (float4*)ws;
        for (int i = tid; i < HID * G4 / 4; i += 448) wdst[i] = wsrc[i];
    }
    float c[RPT];
    float h0j = h0[j], c0j = c0[j];
    #pragma unroll
    for (int p = 0; p < 5; p++) hs2[(ry * 5 + p) * 112 + j] = make_float2(h0j, h0j);
    #pragma unroll
    for (int i = 0; i < RPT; i++) c[i] = c0j;
    __syncthreads();

    for (int t = 0; t < T_STEPS; t++) {
        ull accp[5][4];
        #pragma unroll
        for (int p = 0; p < 5; p++)
            #pragma unroll
            for (int g = 0; g < 4; g++) accp[p][g] = 0ull;

        const ulonglong2* hv2 = (const ulonglong2*)hs2;
        #pragma unroll 2
        for (int kq = 0; kq < 56; kq++) {
            int k = kq * 2;
            ulonglong2 hv[5];
            #pragma unroll
            for (int p = 0; p < 5; p++)
                hv[p] = hv2[((ry * 5 + p) * 112 + k) >> 1];
            const float* wk = ws + k * G4 + j;
            ull wd0[4], wd1[4];
            #pragma unroll
            for (int g = 0; g < 4; g++) {
                wd0[g] = dup2(wk[g * 112]);
                wd1[g] = dup2(wk[G4 + g * 112]);
            }
            #pragma unroll
            for (int p = 0; p < 5; p++)
                #pragma unroll
                for (int g = 0; g < 4; g++) {
                    fma2(accp[p][g], hv[p].x, wd0[g]);
                    fma2(accp[p][g], hv[p].y, wd1[g]);
                }
        }
        __syncthreads();

        const float* gxb = g_gx + ((size_t)t * NB + mb + ry * RPT) * G4 + j;
        #pragma unroll
        for (int p = 0; p < 5; p++) {
            float a0[4], a1[4];
            #pragma unroll
            for (int g = 0; g < 4; g++) unpack2(accp[p][g], a0[g], a1[g]);
            const float* gp0 = gxb + (size_t)(2 * p) * G4;
            const float* gp1 = gp0 + G4;

            float I0 = fsig(a0[0] + gp0[0]);
            float F0 = fsig(a0[1] + gp0[112]);
            float G0 = ftanh(a0[2] + gp0[224]);
            float O0 = fsig(a0[3] + gp0[336]);
            c[2 * p] = fmaf(F0, c[2 * p], I0 * G0);
            float hA = O0 * ftanh(c[2 * p]);

            float I1 = fsig(a1[0] + gp1[0]);
            float F1 = fsig(a1[1] + gp1[112]);
            float G1 = ftanh(a1[2] + gp1[224]);
            float O1 = fsig(a1[3] + gp1[336]);
            c[2 * p + 1] = fmaf(F1, c[2 * p + 1], I1 * G1);
            float hB = O1 * ftanh(c[2 * p + 1]);

            hs2[(ry * 5 + p) * 112 + j] = make_float2(hA, hB);
        }
        __syncthreads();
    }

    if (tid < ROWS_PER_BLK) {
        int pair = tid >> 1, comp = tid & 1;
        float l[3];
        #pragma unroll
        for (int o = 0; o < 3; o++) {
            float a = bf[o];
            const float* wo = wf + o * 112;
            #pragma unroll 4
            for (int k = 0; k < 112; k++) {
                float2 v = hs2[pair * 112 + k];
                a = fmaf(comp ? v.y : v.x, wo[k], a);
            }
            l[o] = a;
        }
        float m = fmaxf(l[0], fmaxf(l[1], l[2]));
        float e0 = expf(l[0] - m), e1 = expf(l[1] - m), e2 = expf(l[2] - m);
        float s = 1.f / (e0 + e1 + e2);
        float* op = out + (size_t)(mb + tid) * 3;
        op[0] = e0 * s; op[1] = e1 * s; op[2] = e2 * s;
    }
}

// ---------------------------------------------------------------------------
extern "C" void kernel_launch(void* const* d_in, const int* in_sizes, int n_in,
                              void* d_out, int out_size) {
    const float* imgs = (const float*)d_in[0];
    const float* w1   = (const float*)d_in[1];
    const float* b1   = (const float*)d_in[2];
    const float* w2   = (const float*)d_in[3];
    const float* b2   = (const float*)d_in[4];
    const float* w3   = (const float*)d_in[5];
    const float* b3   = (const float*)d_in[6];
    const float* w_ih = (const float*)d_in[7];
    const float* w_hh = (const float*)d_in[8];
    const float* b_ih = (const float*)d_in[9];
    const float* b_hh = (const float*)d_in[10];
    const float* wf   = (const float*)d_in[11];
    const float* bf   = (const float*)d_in[12];
    const float* h0   = (const float*)d_in[13];
    const float* c0   = (const float*)d_in[14];

    const int lstm_smem = HID * G4 * 4 + 20 * 112 * 8;  // 218,624 B
    cudaFuncSetAttribute(k_lstm, cudaFuncAttributeMaxDynamicSharedMemorySize, lstm_smem);

    k_transpose<<<(HID * G4 + 255) / 256, 256>>>(w_hh);
    k_conv1<<<NIMG / 2, 256>>>(imgs, w1, b1);
    k_conv2<<<NIMG / 2, 256>>>(w2, b2);
    k_conv3<<<NIMG / 4, 256>>>(w3, b3);
    k_gatesx<<<(T_STEPS * NB) / 64, 448>>>(w_ih, b_ih, b_hh);
    k_lstm<<<LSTM_BLOCKS, 448, lstm_smem>>>(h0, c0, wf, bf, (float*)d_out);
}